// round 9
// baseline (speedup 1.0000x reference)
#include <cuda_runtime.h>
#include <cstdint>
#include <cstddef>

#define B_ 256
#define S_ 512
#define T_ 128

typedef unsigned long long ull;

__device__ float g_acc;        // zero-init; reset by last CTA each run
__device__ unsigned g_done;    // zero-init; reset by last CTA each run

// Packed fp32x2 ops (sm_103a).
#define FMA2(d, a, b, c) asm("fma.rn.f32x2 %0, %1, %2, %3;" : "=l"(d) : "l"(a), "l"(b), "l"(c))
#define ADD2(d, a, b)    asm("add.rn.f32x2 %0, %1, %2;"     : "=l"(d) : "l"(a), "l"(b))
#define PACK2(d, lo, hi) asm("mov.b64 %0, {%1, %2};"        : "=l"(d) : "f"(lo), "f"(hi))
#define UNPK2(lo, hi, s) asm("mov.b64 {%0, %1}, %2;"        : "=f"(lo), "=f"(hi) : "l"(s))

// ---------------------------------------------------------------------------
// Fully fused CRF: dtype probe + gold + forward partition + output, one launch.
// One batch per CTA (grid=256), 256 threads: thread (j = tid>>1, h = tid&1)
// owns half of column j's 128-term dot product; lane pairs combine via
// shfl_xor(1). Rescale every 4 steps (fp32 headroom: growth <= ~e^56 < e^88).
// One __syncthreads per recursion step.
// ---------------------------------------------------------------------------
__global__ void __launch_bounds__(256, 2) crf_fused(
    const float* __restrict__ em, const float* __restrict__ tr,
    const void* __restrict__ tags, const unsigned char* __restrict__ mask,
    float* __restrict__ out) {

    __shared__ __align__(16) float s_alpha[2][T_];
    __shared__ __align__(16) float s_wmax[8];
    __shared__ float s_red[8];
    __shared__ int   s_flags[2];

    const int tid  = threadIdx.x;
    const int w    = tid >> 5;
    const int lane = tid & 31;
    const int j    = tid >> 1;       // column 0..127
    const int h    = tid & 1;        // half: rows [64h, 64h+64)
    const size_t b = blockIdx.x;

    // ---- dtype probe (per-CTA; reads only first 256B of tags, L2-cached) ---
    // JAX x64-off silently downcasts int64 tags to int32. Tags < 128, so for a
    // true int64 buffer every odd int32 word is 0; P(false positive) ~ 128^-64.
    if (tid == 0) {
        const int* t32 = (const int*)tags;
        int all0 = 1;
        #pragma unroll
        for (int i = 0; i < 64; ++i)
            if (t32[2 * i + 1] != 0) all0 = 0;
        s_flags[0] = all0;
        const unsigned char* mk = mask;
        s_flags[1] = (mk[0] != 0 && mk[1] == 0 && mk[2] == 0 && mk[3] == 0) ? 4 : 1;
    }
    __syncthreads();
    const int t64 = s_flags[0], mst = s_flags[1];

    // ---- gold score for this batch (negated into g_acc) --------------------
    {
        const long long* tg64 = (const long long*)tags + b * S_;
        const int*       tg32 = (const int*)tags + b * S_;
        const unsigned char* mk = mask + b * S_ * mst;
        float sum = 0.0f;
        for (int t = tid; t < S_; t += 256) {
            int tag = t64 ? (int)tg64[t] : tg32[t];
            float m = mk[(size_t)t * mst] ? 1.0f : 0.0f;
            sum += em[(b * S_ + t) * T_ + tag] * m;
            if (t + 1 < S_) {
                int tag2 = t64 ? (int)tg64[t + 1] : tg32[t + 1];
                float m2 = mk[(size_t)(t + 1) * mst] ? 1.0f : 0.0f;
                sum += tr[tag * T_ + tag2] * m2;
            }
        }
        for (int off = 16; off; off >>= 1)
            sum += __shfl_xor_sync(0xffffffffu, sum, off);
        if (lane == 0) s_red[w] = sum;
        __syncthreads();
        if (tid == 0) {
            float s = 0.0f;
            #pragma unroll
            for (int k = 0; k < 8; ++k) s += s_red[k];
            atomicAdd(&g_acc, -s);
        }
        __syncthreads();   // s_red reused below
    }

    // ---- M half-column: Mc[k] = (exp(T[64h+2k][j]), exp(T[64h+2k+1][j])) ---
    ull Mc[32];
    {
        const int r0 = 64 * h;
        #pragma unroll
        for (int k = 0; k < 32; ++k) {
            float m0 = expf(tr[(r0 + 2 * k) * T_ + j]);
            float m1 = expf(tr[(r0 + 2 * k + 1) * T_ + j]);
            PACK2(Mc[k], m0, m1);
        }
    }

    // ---- init: alpha_0 = exp(e0 - max(e0)), logacc = max(e0) ---------------
    float e0 = em[(b * S_ + 0) * T_ + j];
    float pm = e0;
    for (int off = 16; off; off >>= 1)
        pm = fmaxf(pm, __shfl_xor_sync(0xffffffffu, pm, off));
    if (lane == 0) s_red[w] = pm;
    __syncthreads();
    float m0v = fmaxf(fmaxf(fmaxf(s_red[0], s_red[1]), fmaxf(s_red[2], s_red[3])),
                      fmaxf(fmaxf(s_red[4], s_red[5]), fmaxf(s_red[6], s_red[7])));
    float logacc = m0v;                       // uniform across CTA
    if (h == 0) s_alpha[0][j] = __expf(e0 - m0v);
    if (tid < 8) s_wmax[tid] = 1.0f;          // max(alpha_0) = 1

    // emission prefetch ring (3 deep); lane pairs read same addr (bcast LDG)
    float e_cur = em[(b * S_ + 1) * T_ + j];
    float e_nx  = em[(b * S_ + 2) * T_ + j];
    float e_nx2 = em[(b * S_ + 3) * T_ + j];
    __syncthreads();

    // ---- main recursion: one barrier/step, rescale every 4 steps -----------
    float v = 0.0f;
    #pragma unroll 1
    for (int t = 1; t < S_; ++t) {
        const int rb = (t - 1) & 1, wb = t & 1;

        float scale = 1.0f;
        if ((t & 3) == 1) {                   // apply rescale (uniform branch)
            float m = fmaxf(
                fmaxf(fmaxf(s_wmax[0], s_wmax[1]), fmaxf(s_wmax[2], s_wmax[3])),
                fmaxf(fmaxf(s_wmax[4], s_wmax[5]), fmaxf(s_wmax[6], s_wmax[7])));
            scale = __fdividef(1.0f, m);
            logacc += __logf(m);
        }
        float ex = __expf(e_cur);

        // 64-term half dot: 16 broadcast LDS.128 + 32 FMA2 in 4 chains
        const ulonglong2* A = (const ulonglong2*)&s_alpha[rb][64 * h];
        ull a0 = 0ull, a1 = 0ull, a2 = 0ull, a3 = 0ull;
        #pragma unroll
        for (int k = 0; k < 16; k += 2) {
            ulonglong2 p  = A[k];
            ulonglong2 q2 = A[k + 1];
            FMA2(a0, p.x,  Mc[2 * k],     a0);
            FMA2(a1, p.y,  Mc[2 * k + 1], a1);
            FMA2(a2, q2.x, Mc[2 * k + 2], a2);
            FMA2(a3, q2.y, Mc[2 * k + 3], a3);
        }
        ADD2(a0, a0, a1);
        ADD2(a2, a2, a3);
        ADD2(a0, a0, a2);
        float lo, hi;
        UNPK2(lo, hi, a0);
        float dot = lo + hi;
        dot += __shfl_xor_sync(0xffffffffu, dot, 1);   // combine halves
        v = dot * scale * ex;

        // rotate prefetch ring
        e_cur = e_nx; e_nx = e_nx2;
        int t3 = (t + 3 < S_) ? t + 3 : S_ - 1;
        e_nx2 = em[(b * S_ + t3) * T_ + j];

        if (h == 0) s_alpha[wb][j] = v;
        if ((t & 3) == 0) {                   // publish max (v > 0: uint cmp ok)
            unsigned wmx = __reduce_max_sync(0xffffffffu, __float_as_uint(v));
            if (lane == 0) s_wmax[w] = __uint_as_float(wmx);
        }
        __syncthreads();
    }

    // ---- finish: partition_b = log(sum_j v) + logacc -----------------------
    float s = (h == 0) ? v : 0.0f;
    for (int off = 16; off; off >>= 1)
        s += __shfl_xor_sync(0xffffffffu, s, off);
    if (lane == 0) s_red[w] = s;
    __syncthreads();
    if (tid == 0) {
        float tot = 0.0f;
        #pragma unroll
        for (int k = 0; k < 8; ++k) tot += s_red[k];
        atomicAdd(&g_acc, logf(tot) + logacc);
        __threadfence();
        unsigned r = atomicAdd(&g_done, 1u);
        if (r == B_ - 1) {                    // last CTA: publish + reset
            float res = atomicExch(&g_acc, 0.0f);
            out[0] = res;
            atomicExch(&g_done, 0u);
        }
    }
}

extern "C" void kernel_launch(void* const* d_in, const int* in_sizes, int n_in,
                              void* d_out, int out_size) {
    const float* em         = (const float*)d_in[0];
    const void* tags        = d_in[1];
    const unsigned char* mk = (const unsigned char*)d_in[2];
    const float* tr         = (const float*)d_in[3];

    crf_fused<<<B_, 256>>>(em, tr, tags, mk, (float*)d_out);
}

// round 11
// speedup vs baseline: 1.1956x; 1.1956x over previous
#include <cuda_runtime.h>
#include <cstdint>
#include <cstddef>

#define B_ 256
#define S_ 512
#define T_ 128
#define GRID_ (B_ / 2)

typedef unsigned long long ull;

__device__ float g_acc;        // zero-init; reset by last CTA each run
__device__ unsigned g_done;    // zero-init; reset by last CTA each run

// Packed fp32x2 ops (sm_103a).
#define FMA2(d, a, b, c) asm("fma.rn.f32x2 %0, %1, %2, %3;" : "=l"(d) : "l"(a), "l"(b), "l"(c))
#define ADD2(d, a, b)    asm("add.rn.f32x2 %0, %1, %2;"     : "=l"(d) : "l"(a), "l"(b))
#define PACK2(d, lo, hi) asm("mov.b64 %0, {%1, %2};"        : "=l"(d) : "f"(lo), "f"(hi))
#define UNPK2(lo, hi, s) asm("mov.b64 {%0, %1}, %2;"        : "=f"(lo), "=f"(hi) : "l"(s))

// ---------------------------------------------------------------------------
// Fully fused CRF. 2 batches per CTA, 128 threads (thread j = output column),
// grid 128 -> one CTA per SM. All alpha LDS are warp-uniform broadcasts
// (1 wavefront each); M column shared across both batches in 64 f32x2 regs.
// One __syncthreads per step; rescale every 4 steps.
// Inner loop covers ALL 32 ulonglong2 alpha chunks / 64 Mc pairs (R10 bug fix).
// ---------------------------------------------------------------------------
__global__ void __launch_bounds__(128, 1) crf_fused(
    const float* __restrict__ em, const float* __restrict__ tr,
    const void* __restrict__ tags, const unsigned char* __restrict__ mask,
    float* __restrict__ out) {

    __shared__ __align__(16) float s_alpha[2][2][T_];  // [buf][batch][col]
    __shared__ __align__(16) float s_wmax[2][4];       // [batch][warp]
    __shared__ float s_red[8];
    __shared__ int   s_flags[2];

    const int j    = threadIdx.x;    // 0..127 : output column
    const int w    = j >> 5;
    const int lane = j & 31;
    const size_t b0 = (size_t)blockIdx.x * 2;
    const size_t b1 = b0 + 1;

    // ---- dtype probe (JAX x64-off downcasts int64 tags to int32) ----------
    // tags < 128 => int64 buffer has all odd int32 words zero; P(fp) ~128^-64.
    if (j == 0) {
        const int* t32 = (const int*)tags;
        int all0 = 1;
        #pragma unroll
        for (int i = 0; i < 64; ++i)
            if (t32[2 * i + 1] != 0) all0 = 0;
        s_flags[0] = all0;
        const unsigned char* mk = mask;
        s_flags[1] = (mk[0] != 0 && mk[1] == 0 && mk[2] == 0 && mk[3] == 0) ? 4 : 1;
    }
    __syncthreads();
    const int t64 = s_flags[0], mst = s_flags[1];

    // ---- gold score for both batches (negated into g_acc) ------------------
    {
        float sum = 0.0f;
        #pragma unroll
        for (int bb = 0; bb < 2; ++bb) {
            const size_t b = b0 + bb;
            const long long* tg64 = (const long long*)tags + b * S_;
            const int*       tg32 = (const int*)tags + b * S_;
            const unsigned char* mk = mask + b * S_ * mst;
            for (int t = j; t < S_; t += 128) {
                int tag = t64 ? (int)tg64[t] : tg32[t];
                float m = mk[(size_t)t * mst] ? 1.0f : 0.0f;
                sum += em[(b * S_ + t) * T_ + tag] * m;
                if (t + 1 < S_) {
                    int tag2 = t64 ? (int)tg64[t + 1] : tg32[t + 1];
                    float m2 = mk[(size_t)(t + 1) * mst] ? 1.0f : 0.0f;
                    sum += tr[tag * T_ + tag2] * m2;
                }
            }
        }
        for (int off = 16; off; off >>= 1)
            sum += __shfl_xor_sync(0xffffffffu, sum, off);
        if (lane == 0) s_red[w] = sum;
        __syncthreads();
        if (j == 0)
            atomicAdd(&g_acc, -(s_red[0] + s_red[1] + s_red[2] + s_red[3]));
        __syncthreads();   // s_red reused
    }

    // ---- M column j: Mc[k] = (exp(T[2k][j]), exp(T[2k+1][j])) --------------
    ull Mc[64];
    #pragma unroll
    for (int k = 0; k < 64; ++k) {
        float m0 = expf(tr[(2 * k) * T_ + j]);
        float m1 = expf(tr[(2 * k + 1) * T_ + j]);
        PACK2(Mc[k], m0, m1);
    }

    // ---- init: alpha_0 = exp(e0 - max(e0)) per batch ------------------------
    float e00 = em[(b0 * S_ + 0) * T_ + j];
    float e01 = em[(b1 * S_ + 0) * T_ + j];
    float p0 = e00, p1 = e01;
    for (int off = 16; off; off >>= 1) {
        p0 = fmaxf(p0, __shfl_xor_sync(0xffffffffu, p0, off));
        p1 = fmaxf(p1, __shfl_xor_sync(0xffffffffu, p1, off));
    }
    if (lane == 0) { s_red[w] = p0; s_red[4 + w] = p1; }
    __syncthreads();
    float mx0 = fmaxf(fmaxf(s_red[0], s_red[1]), fmaxf(s_red[2], s_red[3]));
    float mx1 = fmaxf(fmaxf(s_red[4], s_red[5]), fmaxf(s_red[6], s_red[7]));
    float logacc0 = mx0, logacc1 = mx1;          // uniform across CTA
    s_alpha[0][0][j] = __expf(e00 - mx0);
    s_alpha[0][1][j] = __expf(e01 - mx1);
    if (j < 8) s_wmax[j >> 2][j & 3] = 1.0f;     // max(alpha_0) = 1

    // emission prefetch rings (3 deep) for both batches
    float ec0 = em[(b0 * S_ + 1) * T_ + j], ec1 = em[(b1 * S_ + 1) * T_ + j];
    float en0 = em[(b0 * S_ + 2) * T_ + j], en1 = em[(b1 * S_ + 2) * T_ + j];
    float ef0 = em[(b0 * S_ + 3) * T_ + j], ef1 = em[(b1 * S_ + 3) * T_ + j];
    __syncthreads();

    // ---- main recursion: one barrier/step, rescale every 4 steps ------------
    float v0 = 0.0f, v1 = 0.0f;
    #pragma unroll 1
    for (int t = 1; t < S_; ++t) {
        const int rb = (t - 1) & 1, wb = t & 1;

        // fire next prefetch LDGs first so DRAM latency hides under FMA block
        int t3 = (t + 3 < S_) ? t + 3 : S_ - 1;
        float eg0 = em[(b0 * S_ + t3) * T_ + j];
        float eg1 = em[(b1 * S_ + t3) * T_ + j];

        float scale0 = 1.0f, scale1 = 1.0f;
        if ((t & 3) == 1) {                       // uniform branch
            float4 w0 = *(const float4*)s_wmax[0];
            float4 w1 = *(const float4*)s_wmax[1];
            float m0 = fmaxf(fmaxf(w0.x, w0.y), fmaxf(w0.z, w0.w));
            float m1 = fmaxf(fmaxf(w1.x, w1.y), fmaxf(w1.z, w1.w));
            scale0 = __fdividef(1.0f, m0);
            scale1 = __fdividef(1.0f, m1);
            logacc0 += __logf(m0);
            logacc1 += __logf(m1);
        }
        float ex0 = __expf(ec0);
        float ex1 = __expf(ec1);

        // FULL 128-term dots for both batches: 64 broadcast LDS.128 total,
        // 128 FMA2 in 8 independent chains (depth 16 each).
        const ulonglong2* A0 = (const ulonglong2*)s_alpha[rb][0];
        const ulonglong2* A1 = (const ulonglong2*)s_alpha[rb][1];
        ull a00 = 0ull, a01 = 0ull, a02 = 0ull, a03 = 0ull;
        ull a10 = 0ull, a11 = 0ull, a12 = 0ull, a13 = 0ull;
        #pragma unroll
        for (int k = 0; k < 32; k += 2) {         // <-- full range (bug fix)
            ulonglong2 x0 = A0[k];
            ulonglong2 y0 = A0[k + 1];
            ulonglong2 x1 = A1[k];
            ulonglong2 y1 = A1[k + 1];
            FMA2(a00, x0.x, Mc[2 * k],     a00);
            FMA2(a10, x1.x, Mc[2 * k],     a10);
            FMA2(a01, x0.y, Mc[2 * k + 1], a01);
            FMA2(a11, x1.y, Mc[2 * k + 1], a11);
            FMA2(a02, y0.x, Mc[2 * k + 2], a02);
            FMA2(a12, y1.x, Mc[2 * k + 2], a12);
            FMA2(a03, y0.y, Mc[2 * k + 3], a03);
            FMA2(a13, y1.y, Mc[2 * k + 3], a13);
        }
        ADD2(a00, a00, a01); ADD2(a02, a02, a03); ADD2(a00, a00, a02);
        ADD2(a10, a10, a11); ADD2(a12, a12, a13); ADD2(a10, a10, a12);
        float lo0, hi0, lo1, hi1;
        UNPK2(lo0, hi0, a00);
        UNPK2(lo1, hi1, a10);
        v0 = (lo0 + hi0) * scale0 * ex0;
        v1 = (lo1 + hi1) * scale1 * ex1;

        // rotate rings
        ec0 = en0; en0 = ef0; ef0 = eg0;
        ec1 = en1; en1 = ef1; ef1 = eg1;

        s_alpha[wb][0][j] = v0;
        s_alpha[wb][1][j] = v1;
        if ((t & 3) == 0) {                       // publish maxes (v > 0)
            unsigned m0 = __reduce_max_sync(0xffffffffu, __float_as_uint(v0));
            unsigned m1 = __reduce_max_sync(0xffffffffu, __float_as_uint(v1));
            if (lane == 0) {
                s_wmax[0][w] = __uint_as_float(m0);
                s_wmax[1][w] = __uint_as_float(m1);
            }
        }
        __syncthreads();
    }

    // ---- finish: partition_b = log(sum_j v_b) + logacc_b --------------------
    float s0 = v0, s1 = v1;
    for (int off = 16; off; off >>= 1) {
        s0 += __shfl_xor_sync(0xffffffffu, s0, off);
        s1 += __shfl_xor_sync(0xffffffffu, s1, off);
    }
    if (lane == 0) { s_red[w] = s0; s_red[4 + w] = s1; }
    __syncthreads();
    if (j == 0) {
        float tot0 = s_red[0] + s_red[1] + s_red[2] + s_red[3];
        float tot1 = s_red[4] + s_red[5] + s_red[6] + s_red[7];
        atomicAdd(&g_acc, logf(tot0) + logacc0 + logf(tot1) + logacc1);
        __threadfence();
        unsigned r = atomicAdd(&g_done, 1u);
        if (r == GRID_ - 1) {                     // last CTA: publish + reset
            float res = atomicExch(&g_acc, 0.0f);
            out[0] = res;
            atomicExch(&g_done, 0u);
        }
    }
}

extern "C" void kernel_launch(void* const* d_in, const int* in_sizes, int n_in,
                              void* d_out, int out_size) {
    const float* em         = (const float*)d_in[0];
    const void* tags        = d_in[1];
    const unsigned char* mk = (const unsigned char*)d_in[2];
    const float* tr         = (const float*)d_in[3];

    crf_fused<<<GRID_, 128>>>(em, tr, tags, mk, (float*)d_out);
}

// round 13
// speedup vs baseline: 1.7768x; 1.4861x over previous
#include <cuda_runtime.h>
#include <cstdint>
#include <cstddef>

#define B_ 256
#define S_ 512
#define T_ 128

typedef unsigned long long ull;

__device__ float g_acc;        // zero-init; reset by last CTA each run
__device__ unsigned g_done;    // zero-init; reset by last CTA each run

// Packed fp32x2 ops (sm_103a).
#define FMA2(d, a, b, c) asm("fma.rn.f32x2 %0, %1, %2, %3;" : "=l"(d) : "l"(a), "l"(b), "l"(c))
#define ADD2(d, a, b)    asm("add.rn.f32x2 %0, %1, %2;"     : "=l"(d) : "l"(a), "l"(b))
#define PACK2(d, lo, hi) asm("mov.b64 %0, {%1, %2};"        : "=l"(d) : "f"(lo), "f"(hi))
#define UNPK2(lo, hi, s) asm("mov.b64 {%0, %1}, %2;"        : "=f"(lo), "=f"(hi) : "l"(s))

// ---------------------------------------------------------------------------
// Fully fused CRF. 1 batch per CTA (grid 256), 128 threads (thread = column j),
// __launch_bounds__(128,2) -> 2 CTAs/SM = 2 independent warps/SMSP for latency
// hiding. All alpha LDS are warp-uniform broadcasts. No max-reductions at all:
// rescale every step by alpha_prev[0] (any CTA-uniform positive scale is
// algebraically exact; values stay within ~e^15 of 1, far from fp32 limits).
// One __syncthreads per step.
// ---------------------------------------------------------------------------
__global__ void __launch_bounds__(128, 2) crf_fused(
    const float* __restrict__ em, const float* __restrict__ tr,
    const void* __restrict__ tags, const unsigned char* __restrict__ mask,
    float* __restrict__ out) {

    __shared__ __align__(16) float s_alpha[2][T_];   // [buf][col]
    __shared__ float s_red[4];
    __shared__ int   s_flags[2];

    const int j    = threadIdx.x;    // 0..127 : output column
    const int w    = j >> 5;
    const int lane = j & 31;
    const size_t b = blockIdx.x;

    // ---- dtype probe (JAX x64-off downcasts int64 tags to int32) ----------
    // tags < 128 => int64 buffer has all odd int32 words zero; P(fp) ~128^-64.
    if (j == 0) {
        const int* t32 = (const int*)tags;
        int all0 = 1;
        #pragma unroll
        for (int i = 0; i < 64; ++i)
            if (t32[2 * i + 1] != 0) all0 = 0;
        s_flags[0] = all0;
        const unsigned char* mk = mask;
        s_flags[1] = (mk[0] != 0 && mk[1] == 0 && mk[2] == 0 && mk[3] == 0) ? 4 : 1;
    }
    __syncthreads();
    const int t64 = s_flags[0], mst = s_flags[1];

    // ---- gold score for this batch (negated into g_acc) --------------------
    {
        const long long* tg64 = (const long long*)tags + b * S_;
        const int*       tg32 = (const int*)tags + b * S_;
        const unsigned char* mk = mask + b * S_ * mst;
        float sum = 0.0f;
        for (int t = j; t < S_; t += 128) {
            int tag = t64 ? (int)tg64[t] : tg32[t];
            float m = mk[(size_t)t * mst] ? 1.0f : 0.0f;
            sum += em[(b * S_ + t) * T_ + tag] * m;
            if (t + 1 < S_) {
                int tag2 = t64 ? (int)tg64[t + 1] : tg32[t + 1];
                float m2 = mk[(size_t)(t + 1) * mst] ? 1.0f : 0.0f;
                sum += tr[tag * T_ + tag2] * m2;
            }
        }
        for (int off = 16; off; off >>= 1)
            sum += __shfl_xor_sync(0xffffffffu, sum, off);
        if (lane == 0) s_red[w] = sum;
        __syncthreads();
        if (j == 0)
            atomicAdd(&g_acc, -(s_red[0] + s_red[1] + s_red[2] + s_red[3]));
        __syncthreads();   // s_red reused at the end
    }

    // ---- M column j: Mc[k] = (exp(T[2k][j]), exp(T[2k+1][j])) --------------
    ull Mc[64];
    #pragma unroll
    for (int k = 0; k < 64; ++k) {
        float m0 = expf(tr[(2 * k) * T_ + j]);
        float m1 = expf(tr[(2 * k + 1) * T_ + j]);
        PACK2(Mc[k], m0, m1);
    }

    // ---- init: alpha_0 = exp(e0), logacc = 0 (no reduction needed) ---------
    float e0 = em[(b * S_ + 0) * T_ + j];
    s_alpha[0][j] = __expf(e0);
    float logacc = 0.0f;                 // uniform across CTA

    // emission prefetch ring (3 deep)
    float e_cur = em[(b * S_ + 1) * T_ + j];
    float e_nx  = em[(b * S_ + 2) * T_ + j];
    float e_nx2 = em[(b * S_ + 3) * T_ + j];
    __syncthreads();

    // ---- main recursion: one barrier/step, scale = 1/alpha_prev[0] ----------
    float v = 0.0f;
    #pragma unroll 1
    for (int t = 1; t < S_; ++t) {
        const int rb = (t - 1) & 1, wb = t & 1;

        // CTA-uniform rescale from previous alpha's first element (broadcast)
        float c = s_alpha[rb][0];
        float scale = __fdividef(1.0f, c);
        logacc += __logf(c);

        // fire next prefetch LDG early so DRAM latency hides under FMA block
        int t3 = (t + 3 < S_) ? t + 3 : S_ - 1;
        float eg = em[(b * S_ + t3) * T_ + j];

        float ex = __expf(e_cur);

        // 128-term dot: 32 broadcast LDS.128 + 64 FMA2 in 8 chains (depth 8)
        const ulonglong2* A = (const ulonglong2*)s_alpha[rb];
        ull a0 = 0ull, a1 = 0ull, a2 = 0ull, a3 = 0ull;
        ull a4 = 0ull, a5 = 0ull, a6 = 0ull, a7 = 0ull;
        #pragma unroll
        for (int k = 0; k < 32; k += 4) {
            ulonglong2 x0 = A[k];
            ulonglong2 x1 = A[k + 1];
            ulonglong2 x2 = A[k + 2];
            ulonglong2 x3 = A[k + 3];
            FMA2(a0, x0.x, Mc[2 * k],     a0);
            FMA2(a1, x0.y, Mc[2 * k + 1], a1);
            FMA2(a2, x1.x, Mc[2 * k + 2], a2);
            FMA2(a3, x1.y, Mc[2 * k + 3], a3);
            FMA2(a4, x2.x, Mc[2 * k + 4], a4);
            FMA2(a5, x2.y, Mc[2 * k + 5], a5);
            FMA2(a6, x3.x, Mc[2 * k + 6], a6);
            FMA2(a7, x3.y, Mc[2 * k + 7], a7);
        }
        ADD2(a0, a0, a1); ADD2(a2, a2, a3); ADD2(a4, a4, a5); ADD2(a6, a6, a7);
        ADD2(a0, a0, a2); ADD2(a4, a4, a6);
        ADD2(a0, a0, a4);
        float lo, hi;
        UNPK2(lo, hi, a0);
        v = (lo + hi) * scale * ex;

        // rotate ring
        e_cur = e_nx; e_nx = e_nx2; e_nx2 = eg;

        s_alpha[wb][j] = v;
        __syncthreads();
    }

    // ---- finish: partition_b = log(sum_j v) + logacc -----------------------
    float s = v;
    for (int off = 16; off; off >>= 1)
        s += __shfl_xor_sync(0xffffffffu, s, off);
    if (lane == 0) s_red[w] = s;
    __syncthreads();
    if (j == 0) {
        float tot = s_red[0] + s_red[1] + s_red[2] + s_red[3];
        atomicAdd(&g_acc, logf(tot) + logacc);
        __threadfence();
        unsigned r = atomicAdd(&g_done, 1u);
        if (r == B_ - 1) {                 // last CTA: publish + reset
            float res = atomicExch(&g_acc, 0.0f);
            out[0] = res;
            atomicExch(&g_done, 0u);
        }
    }
}

extern "C" void kernel_launch(void* const* d_in, const int* in_sizes, int n_in,
                              void* d_out, int out_size) {
    const float* em         = (const float*)d_in[0];
    const void* tags        = d_in[1];
    const unsigned char* mk = (const unsigned char*)d_in[2];
    const float* tr         = (const float*)d_in[3];

    crf_fused<<<B_, 128>>>(em, tr, tags, mk, (float*)d_out);
}